// round 3
// baseline (speedup 1.0000x reference)
#include <cuda_runtime.h>
#include <cstdint>

#define GRID   32
#define NCELL  (GRID*GRID*GRID)
#define BMAX   4
#define MMAX   4096
#define DOMAIN 4.5f
#define F_INF  __int_as_float(0x7f800000)

// ---------------- device scratch (allocation-free rule) ----------------
__device__ int      g_cnt[BMAX][NCELL];    // counts, then reused as scatter cursors
__device__ uint32_t g_tbl[BMAX][NCELL];    // start<<16 | cnt
__device__ int      g_ptcell[BMAX][MMAX];  // cell id per sparse point
__device__ float4   g_pts[BMAX][MMAX];     // cell-sorted: (x,y,z,|p|^2) scaled
__device__ int      g_pidx[BMAX][MMAX];    // cell-sorted: original index

__device__ __forceinline__ float decode_scalar_f(const void* p) {
    int iv = *(const int*)p;
    if (iv >= -1000000 && iv <= 1000000) return (float)iv;  // plausible int
    return __int_as_float(iv);                              // else float bits
}

__device__ __forceinline__ int clampi(int v, int lo, int hi) {
    return v < lo ? lo : (v > hi ? hi : v);
}

// ---------------- k1: zero counts ----------------
__global__ void zero_kernel() {
    int total = BMAX * NCELL;
    for (int i = blockIdx.x * blockDim.x + threadIdx.x; i < total;
         i += gridDim.x * blockDim.x)
        ((int*)g_cnt)[i] = 0;
}

// ---------------- k2: bin sparse points ----------------
__global__ void bin_kernel(const float* __restrict__ sxyz,
                           const void* __restrict__ rf_ptr, int M) {
    int gid = blockIdx.x * blockDim.x + threadIdx.x;
    if (gid >= BMAX * M) return;
    int b = gid / M, m = gid - b * M;

    float inv_sigma = 1.0f / (rf_ptr ? decode_scalar_f(rf_ptr) : 1.0f);
    const float invh = (float)GRID / (2.0f * DOMAIN);

    const float* P = sxyz + (size_t)b * 3 * M;
    float x = P[m] * inv_sigma;
    float y = P[M + m] * inv_sigma;
    float z = P[2 * M + m] * inv_sigma;

    int cx = clampi((int)floorf((x + DOMAIN) * invh), 0, GRID - 1);
    int cy = clampi((int)floorf((y + DOMAIN) * invh), 0, GRID - 1);
    int cz = clampi((int)floorf((z + DOMAIN) * invh), 0, GRID - 1);
    int c = (cz * GRID + cy) * GRID + cx;
    g_ptcell[b][m] = c;
    atomicAdd(&g_cnt[b][c], 1);
}

// ---------------- k3: per-batch exclusive scan (1 block per batch) ----------------
__global__ void scan_kernel() {
    __shared__ int sh[1024];
    __shared__ int s_carry;
    int b = blockIdx.x;
    int t = threadIdx.x;
    if (t == 0) s_carry = 0;
    __syncthreads();

    for (int base = 0; base < NCELL; base += 1024) {
        int v = g_cnt[b][base + t];
        sh[t] = v;
        __syncthreads();
        // Hillis-Steele inclusive scan
        for (int off = 1; off < 1024; off <<= 1) {
            int y = (t >= off) ? sh[t - off] : 0;
            __syncthreads();
            sh[t] += y;
            __syncthreads();
        }
        int carry = s_carry;
        int total = sh[1023];
        int start = carry + sh[t] - v;   // exclusive
        g_tbl[b][base + t] = ((uint32_t)start << 16) | (uint32_t)v;
        g_cnt[b][base + t] = start;      // becomes scatter cursor
        __syncthreads();
        if (t == 0) s_carry = carry + total;
        __syncthreads();
    }
}

// ---------------- k4: scatter into cell-sorted order ----------------
__global__ void scatter_kernel(const float* __restrict__ sxyz,
                               const void* __restrict__ rf_ptr, int M) {
    int gid = blockIdx.x * blockDim.x + threadIdx.x;
    if (gid >= BMAX * M) return;
    int b = gid / M, m = gid - b * M;

    float inv_sigma = 1.0f / (rf_ptr ? decode_scalar_f(rf_ptr) : 1.0f);
    const float* P = sxyz + (size_t)b * 3 * M;
    float x = P[m] * inv_sigma;
    float y = P[M + m] * inv_sigma;
    float z = P[2 * M + m] * inv_sigma;
    float p2 = fmaf(x, x, fmaf(y, y, z * z));

    int c = g_ptcell[b][m];
    int pos = atomicAdd(&g_cnt[b][c], 1);
    g_pts[b][pos] = make_float4(x, y, z, p2);
    g_pidx[b][pos] = m;
}

// ---------------- k5: ring-search query kernel ----------------
__global__ void __launch_bounds__(128) query_kernel(
    const float* __restrict__ xyz, const float* __restrict__ sflow,
    const void* __restrict__ rf_ptr, float* __restrict__ out, int N, int M)
{
    const int b = blockIdx.y;
    const int n = blockIdx.x * blockDim.x + threadIdx.x;
    if (n >= N) return;

    const float inv_sigma = 1.0f / (rf_ptr ? decode_scalar_f(rf_ptr) : 1.0f);
    const float h    = (2.0f * DOMAIN) / (float)GRID;
    const float invh = 1.0f / h;

    const size_t qb = (size_t)b * 3 * N;
    const float qx = xyz[qb + n] * inv_sigma;
    const float qy = xyz[qb + N + n] * inv_sigma;
    const float qz = xyz[qb + 2 * N + n] * inv_sigma;
    const float q2 = fmaf(qx, qx, fmaf(qy, qy, qz * qz));
    const float m2x = -2.0f * qx, m2y = -2.0f * qy, m2z = -2.0f * qz;

    const int cx = clampi((int)floorf((qx + DOMAIN) * invh), 0, GRID - 1);
    const int cy = clampi((int)floorf((qy + DOMAIN) * invh), 0, GRID - 1);
    const int cz = clampi((int)floorf((qz + DOMAIN) * invh), 0, GRID - 1);

    // sorted top-5 (ascending squared distance) + indices
    float b0 = F_INF, b1 = F_INF, b2 = F_INF, b3 = F_INF, b4 = F_INF;
    int   i0 = 0, i1 = 0, i2 = 0, i3 = 0, i4 = 0;

    const float MARGIN = 1.0f + 1e-5f;   // guard against fp rounding of dsq

    for (int r = 0; r < GRID; ++r) {
        if (r >= 2) {
            float bound = (float)(r - 1) * h;
            if (b4 * MARGIN <= bound * bound) break;   // b4 finite => 5 found
        }
        int zlo = cz - r < 0 ? 0 : cz - r, zhi = cz + r > GRID - 1 ? GRID - 1 : cz + r;
        int ylo = cy - r < 0 ? 0 : cy - r, yhi = cy + r > GRID - 1 ? GRID - 1 : cy + r;
        int xlo = cx - r < 0 ? 0 : cx - r, xhi = cx + r > GRID - 1 ? GRID - 1 : cx + r;
        for (int z = zlo; z <= zhi; ++z) {
            int az = z - cz; az = az < 0 ? -az : az;
            for (int y = ylo; y <= yhi; ++y) {
                int ay = y - cy; ay = ay < 0 ? -ay : ay;
                int am = az > ay ? az : ay;
                for (int x = xlo; x <= xhi; ++x) {
                    int ax = x - cx; ax = ax < 0 ? -ax : ax;
                    int ch = am > ax ? am : ax;
                    if (ch != r) continue;               // shell only

                    // min distance from query to this cell's box
                    float lox = fmaf((float)x, h, -DOMAIN), hix = lox + h;
                    float loy = fmaf((float)y, h, -DOMAIN), hiy = loy + h;
                    float loz = fmaf((float)z, h, -DOMAIN), hiz = loz + h;
                    float dx = fmaxf(lox - qx, fmaxf(qx - hix, 0.0f));
                    float dy = fmaxf(loy - qy, fmaxf(qy - hiy, 0.0f));
                    float dz = fmaxf(loz - qz, fmaxf(qz - hiz, 0.0f));
                    float md2 = fmaf(dx, dx, fmaf(dy, dy, dz * dz));
                    if (md2 > b4 * MARGIN) continue;

                    uint32_t tbl = g_tbl[b][(z * GRID + y) * GRID + x];
                    int cnt = (int)(tbl & 0xFFFFu);
                    int st  = (int)(tbl >> 16);
                    for (int t = 0; t < cnt; ++t) {
                        float4 p = g_pts[b][st + t];
                        float s = fmaf(m2x, p.x,
                                  fmaf(m2y, p.y,
                                  fmaf(m2z, p.z, q2 + p.w)));
                        if (s < b4) {
                            int j = g_pidx[b][st + t];
                            bool c3 = s < b3, c2 = s < b2, c1 = s < b1, c0 = s < b0;
                            b4 = c3 ? b3 : s;               i4 = c3 ? i3 : j;
                            b3 = c3 ? (c2 ? b2 : s) : b3;   i3 = c3 ? (c2 ? i2 : j) : i3;
                            b2 = c2 ? (c1 ? b1 : s) : b2;   i2 = c2 ? (c1 ? i1 : j) : i2;
                            b1 = c1 ? (c0 ? b0 : s) : b1;   i1 = c1 ? (c0 ? i0 : j) : i1;
                            b0 = c0 ? s : b0;               i0 = c0 ? j : i0;
                        }
                    }
                }
            }
        }
    }

    // true distances (ascending) + softmax over -d + flow gather
    float d0 = sqrtf(fmaxf(b0, 1e-12f));
    float d1 = sqrtf(fmaxf(b1, 1e-12f));
    float d2 = sqrtf(fmaxf(b2, 1e-12f));
    float d3 = sqrtf(fmaxf(b3, 1e-12f));
    float d4 = sqrtf(fmaxf(b4, 1e-12f));

    float w0 = __expf(d0 - d0);
    float w1 = __expf(d0 - d1);
    float w2 = __expf(d0 - d2);
    float w3 = __expf(d0 - d3);
    float w4 = __expf(d0 - d4);
    float inv = 1.0f / (w0 + w1 + w2 + w3 + w4);

    const float* FL = sflow + (size_t)b * 3 * M;
    float fx = w0 * FL[i0] + w1 * FL[i1] + w2 * FL[i2] + w3 * FL[i3] + w4 * FL[i4];
    float fy = w0 * FL[M + i0] + w1 * FL[M + i1] + w2 * FL[M + i2]
             + w3 * FL[M + i3] + w4 * FL[M + i4];
    float fz = w0 * FL[2*M + i0] + w1 * FL[2*M + i1] + w2 * FL[2*M + i2]
             + w3 * FL[2*M + i3] + w4 * FL[2*M + i4];

    out[qb + n]         = fx * inv;
    out[qb + N + n]     = fy * inv;
    out[qb + 2 * N + n] = fz * inv;
}

// ---------------- launch ----------------
extern "C" void kernel_launch(void* const* d_in, const int* in_sizes, int n_in,
                              void* d_out, int out_size) {
    const float* xyz   = (const float*)d_in[0];
    const float* sxyz  = (const float*)d_in[1];
    const float* sflow = (const float*)d_in[2];
    const void*  rf    = (n_in > 3) ? d_in[3] : nullptr;
    float* out = (float*)d_out;

    const int B = BMAX;
    const int N = in_sizes[0] / (3 * B);   // 16384
    int M = in_sizes[1] / (3 * B);         // 4096
    if (M > MMAX) M = MMAX;

    zero_kernel<<<256, 256>>>();
    {
        int tot = B * M;
        bin_kernel<<<(tot + 255) / 256, 256>>>(sxyz, rf, M);
    }
    scan_kernel<<<B, 1024>>>();
    {
        int tot = B * M;
        scatter_kernel<<<(tot + 255) / 256, 256>>>(sxyz, rf, M);
    }
    {
        dim3 blk(128, 1, 1);
        dim3 grd((N + 127) / 128, B, 1);
        query_kernel<<<grd, blk>>>(xyz, sflow, rf, out, N, M);
    }
}